// round 1
// baseline (speedup 1.0000x reference)
#include <cuda_runtime.h>
#include <cstddef>

#define BB      64
#define NOTES   78
#define TT      128
#define IN_DIM  80
#define HID     64
#define G4      256   // 4*HID
#define NHID    2
#define NG      8     // 4*NHID

// 64*128*78*64 fp32 = ~164 MB scratch for time-LSTM hidden outputs,
// laid out as [b][t][note][h] so the note-LSTM reads contiguous rows.
__device__ float g_time_out[(size_t)BB * TT * NOTES * HID];

// ---------------- packed f32x2 helpers ----------------
__device__ __forceinline__ unsigned long long ffma2(unsigned long long a,
                                                    unsigned long long b,
                                                    unsigned long long c) {
    unsigned long long d;
    asm("fma.rn.f32x2 %0, %1, %2, %3;" : "=l"(d) : "l"(a), "l"(b), "l"(c));
    return d;
}
__device__ __forceinline__ unsigned long long pk2(float lo, float hi) {
    unsigned long long r;
    asm("mov.b64 %0, {%1, %2};" : "=l"(r) : "f"(lo), "f"(hi));
    return r;
}
__device__ __forceinline__ float2 up2(unsigned long long a) {
    float2 v;
    asm("mov.b64 {%0, %1}, %2;" : "=f"(v.x), "=f"(v.y) : "l"(a));
    return v;
}

__device__ __forceinline__ float sigm(float v) {
    return 1.0f / (1.0f + expf(-v));
}

// ======================================================================
// Stage A: time LSTM. One CTA per sequence (b, note); 256 threads;
// thread j owns gate row j (i:0-63, f:64-127, g:128-191, o:192-255).
// All weights for row j live in registers as packed f32x2.
// ======================================================================
__global__ void __launch_bounds__(256, 1) time_lstm_kernel(
    const float* __restrict__ x,
    const float* __restrict__ w_ih,
    const float* __restrict__ w_hh,
    const float* __restrict__ b_ih,
    const float* __restrict__ b_hh)
{
    __shared__ float x_sh[TT * IN_DIM];   // 40 KB
    __shared__ float gates[G4];           // activated gates
    __shared__ float h_sh[HID];

    const int seq  = blockIdx.x;          // b*NOTES + note
    const int b    = seq / NOTES;
    const int note = seq % NOTES;
    const int j    = threadIdx.x;

    // ---- stage the whole input sequence into SMEM (coalesced float4) ----
    {
        const float4* xg = (const float4*)(x + (size_t)seq * TT * IN_DIM);
        float4* xs = (float4*)x_sh;
        #pragma unroll
        for (int i = j; i < TT * IN_DIM / 4; i += 256) xs[i] = xg[i];
    }

    // ---- weights for this gate row into registers (packed pairs) ----
    unsigned long long wih[IN_DIM / 2];   // 40 x u64
    unsigned long long whh[HID / 2];      // 32 x u64
    {
        const unsigned long long* wi = (const unsigned long long*)(w_ih + j * IN_DIM);
        const unsigned long long* wh = (const unsigned long long*)(w_hh + j * HID);
        #pragma unroll
        for (int d = 0; d < IN_DIM / 2; d++) wih[d] = wi[d];
        #pragma unroll
        for (int k = 0; k < HID / 2; k++)  whh[k] = wh[k];
    }
    const float bias = b_ih[j] + b_hh[j];

    if (j < HID) h_sh[j] = 0.0f;
    float c = 0.0f;                        // cell state for unit (j & 63), replicated x4
    __syncthreads();

    float* outp = g_time_out + (((size_t)b * TT) * NOTES + note) * HID;

    #pragma unroll 1
    for (int t = 0; t < TT; t++) {
        const unsigned long long* xr = (const unsigned long long*)(x_sh + t * IN_DIM);
        const unsigned long long* hr = (const unsigned long long*)h_sh;

        unsigned long long a0 = pk2(bias, 0.0f);
        unsigned long long a1 = pk2(0.0f, 0.0f);
        unsigned long long a2 = pk2(0.0f, 0.0f);
        unsigned long long a3 = pk2(0.0f, 0.0f);

        #pragma unroll
        for (int d = 0; d < IN_DIM / 2; d += 4) {
            a0 = ffma2(xr[d + 0], wih[d + 0], a0);
            a1 = ffma2(xr[d + 1], wih[d + 1], a1);
            a2 = ffma2(xr[d + 2], wih[d + 2], a2);
            a3 = ffma2(xr[d + 3], wih[d + 3], a3);
        }
        #pragma unroll
        for (int k = 0; k < HID / 2; k += 4) {
            a0 = ffma2(hr[k + 0], whh[k + 0], a0);
            a1 = ffma2(hr[k + 1], whh[k + 1], a1);
            a2 = ffma2(hr[k + 2], whh[k + 2], a2);
            a3 = ffma2(hr[k + 3], whh[k + 3], a3);
        }
        float2 v0 = up2(a0), v1 = up2(a1), v2 = up2(a2), v3 = up2(a3);
        float g = ((v0.x + v0.y) + (v1.x + v1.y)) + ((v2.x + v2.y) + (v3.x + v3.y));

        // gate nonlinearity: rows 128..191 are the candidate gate (tanh)
        float act = ((j & 192) == 128) ? tanhf(g) : sigm(g);
        gates[j] = act;
        __syncthreads();

        // cell/hidden update, replicated across the 4 gate groups
        const int u = j & 63;
        float iv = gates[u];
        float fv = gates[64 + u];
        float gv = gates[128 + u];
        float ov = gates[192 + u];
        c = fv * c + iv * gv;
        float h = ov * tanhf(c);
        if (j < HID) {
            h_sh[j] = h;
            outp[(size_t)t * NOTES * HID + j] = h;
        }
        __syncthreads();
    }
}

// ======================================================================
// Stage B: note LSTM (hidden = 2). One thread per (b, t) sequence,
// 8192 threads total. Weights in SMEM (uniform broadcast reads).
// Writes the thresholded binary output.
// ======================================================================
__global__ void __launch_bounds__(128) note_lstm_kernel(
    const float* __restrict__ w_ih,
    const float* __restrict__ w_hh,
    const float* __restrict__ b_ih,
    const float* __restrict__ b_hh,
    float* __restrict__ out)
{
    __shared__ float wsh[NG * HID];       // 8 x 64
    __shared__ float whhsh[NG * NHID];    // 8 x 2
    __shared__ float bsh[NG];

    const int tid = threadIdx.x;
    for (int i = tid; i < NG * HID; i += 128) wsh[i] = w_ih[i];
    if (tid < NG * NHID) whhsh[tid] = w_hh[tid];
    if (tid < NG)        bsh[tid] = b_ih[tid] + b_hh[tid];
    __syncthreads();

    const int s = blockIdx.x * 128 + tid;          // 0 .. 8191 = b*TT + t
    const float* xin = g_time_out + (size_t)s * NOTES * HID;
    float* op = out + (size_t)s * NOTES * NHID;

    float h0 = 0.f, h1 = 0.f, c0 = 0.f, c1 = 0.f;

    #pragma unroll 1
    for (int note = 0; note < NOTES; note++) {
        const float4* xp = (const float4*)(xin + note * HID);
        float acc[NG];
        #pragma unroll
        for (int jg = 0; jg < NG; jg++) acc[jg] = bsh[jg];

        #pragma unroll
        for (int k4 = 0; k4 < HID / 4; k4++) {
            float4 xv = __ldg(xp + k4);
            const int kb = k4 * 4;
            #pragma unroll
            for (int jg = 0; jg < NG; jg++) {
                acc[jg] += xv.x * wsh[jg * HID + kb + 0];
                acc[jg] += xv.y * wsh[jg * HID + kb + 1];
                acc[jg] += xv.z * wsh[jg * HID + kb + 2];
                acc[jg] += xv.w * wsh[jg * HID + kb + 3];
            }
        }
        #pragma unroll
        for (int jg = 0; jg < NG; jg++)
            acc[jg] += h0 * whhsh[jg * NHID] + h1 * whhsh[jg * NHID + 1];

        // gate order i, f, g, o over 2 hidden units
        float i0 = sigm(acc[0]),  i1 = sigm(acc[1]);
        float f0 = sigm(acc[2]),  f1 = sigm(acc[3]);
        float g0 = tanhf(acc[4]), g1 = tanhf(acc[5]);
        float o0 = sigm(acc[6]),  o1 = sigm(acc[7]);
        c0 = f0 * c0 + i0 * g0;
        c1 = f1 * c1 + i1 * g1;
        h0 = o0 * tanhf(c0);
        h1 = o1 * tanhf(c1);

        op[note * 2 + 0] = (h0 > 0.5f) ? 1.0f : 0.0f;
        op[note * 2 + 1] = (h1 > 0.5f) ? 1.0f : 0.0f;
    }
}

// ======================================================================
extern "C" void kernel_launch(void* const* d_in, const int* in_sizes, int n_in,
                              void* d_out, int out_size)
{
    const float* x      = (const float*)d_in[0];
    const float* w_ih_t = (const float*)d_in[1];
    const float* w_hh_t = (const float*)d_in[2];
    const float* b_ih_t = (const float*)d_in[3];
    const float* b_hh_t = (const float*)d_in[4];
    const float* w_ih_n = (const float*)d_in[5];
    const float* w_hh_n = (const float*)d_in[6];
    const float* b_ih_n = (const float*)d_in[7];
    const float* b_hh_n = (const float*)d_in[8];

    time_lstm_kernel<<<BB * NOTES, 256>>>(x, w_ih_t, w_hh_t, b_ih_t, b_hh_t);
    note_lstm_kernel<<<BB * TT / 128, 128>>>(w_ih_n, w_hh_n, b_ih_n, b_hh_n,
                                             (float*)d_out);
}